// round 4
// baseline (speedup 1.0000x reference)
#include <cuda_runtime.h>
#include <cstdint>

// Problem constants
#define Bn 8
#define Tn 256
#define Un 64
#define Hn 512
#define Fn 1024

// Scratch for intermediate projections (no cudaMalloc allowed)
__device__ float g_a[Bn * Tn * Fn];   // 8 MB: audio @ Wa + bias
__device__ float g_l[Bn * Un * Fn];   // 2 MB: label @ Wl

__device__ __forceinline__ float to_tf32(float x) {
    float r;
    asm("cvt.rna.tf32.f32 %0, %1;" : "=f"(r) : "f"(x));
    return r;
}

// ---------------------------------------------------------------------------
// Kernel 1: fused tf32 tensor-core GEMM, double-buffered.
// Logical A rows: 0..2047 audio (B*T, H), 2048..2559 label (B*U, H).
// BM=128, BN=64, BK=32. 256 threads, warp grid 4(M)x2(N), warp tile 32x32.
// One __syncthreads per K-iter; LDG of next tile overlaps MMA of current.
// ---------------------------------------------------------------------------
__global__ __launch_bounds__(256, 3)
void joint_gemm_tc(const float* __restrict__ audio,
                   const float* __restrict__ label,
                   const float* __restrict__ W,
                   const float* __restrict__ bias)
{
    const int bc = blockIdx.x;          // 0..15  (N tile of 64)
    const int br = blockIdx.y;          // 0..19  (M tile of 128)
    const bool is_audio = (br < 16);

    const float* Abase = is_audio ? (audio + (size_t)br * 128 * Hn)
                                  : (label + (size_t)(br - 16) * 128 * Hn);
    const float* Wbase = W + (is_audio ? 0 : (size_t)Hn * Fn) + bc * 64;
    float* Cbase = is_audio ? (g_a + (size_t)br * 128 * Fn + bc * 64)
                            : (g_l + (size_t)(br - 16) * 128 * Fn + bc * 64);

    // Conflict-free frag loads:
    //  As bank = (36r + k)%32 = 4g + tig + const -> 32 distinct lanes
    //  Bs bank = (72k + n)%32 = 8tig + g + const -> 32 distinct lanes
    __shared__ float As[2][128][36];
    __shared__ float Bs[2][32][72];

    const int tid = threadIdx.x;
    const int warp = tid >> 5;
    const int lane = tid & 31;
    const int warpM = warp >> 1;        // 0..3
    const int warpN = warp & 1;         // 0..1
    const int g = lane >> 2;            // 0..7
    const int tig = lane & 3;           // 0..3

    float c[2][4][4];
#pragma unroll
    for (int mt = 0; mt < 2; mt++)
#pragma unroll
        for (int nt = 0; nt < 4; nt++)
#pragma unroll
            for (int r = 0; r < 4; r++) c[mt][nt][r] = 0.0f;

    // A tile: 128x32 = 1024 float4, 4/thread. B tile: 32x64 = 512 float4, 2/thread.
    const int ar[4] = { (tid + 0) >> 3, (tid + 256) >> 3, (tid + 512) >> 3, (tid + 768) >> 3 };
    const int ac = tid & 7;                 // float4 index along K
    const int bk[2] = { (tid + 0) >> 4, (tid + 256) >> 4 };
    const int bn = tid & 15;                // float4 index along N

    float4 ra[4], rb[2];
    // Prologue: load kt=0 into regs
#pragma unroll
    for (int i = 0; i < 4; i++)
        ra[i] = *(const float4*)(Abase + (size_t)ar[i] * Hn + ac * 4);
#pragma unroll
    for (int i = 0; i < 2; i++)
        rb[i] = *(const float4*)(Wbase + (size_t)bk[i] * Fn + bn * 4);

    const int NITER = Hn / 32;  // 16
    for (int it = 0; it < NITER; it++) {
        const int buf = it & 1;
        // STS staged regs (tf32-rounded)
#pragma unroll
        for (int i = 0; i < 4; i++) {
            float* dst = &As[buf][ar[i]][ac * 4];
            dst[0] = to_tf32(ra[i].x); dst[1] = to_tf32(ra[i].y);
            dst[2] = to_tf32(ra[i].z); dst[3] = to_tf32(ra[i].w);
        }
#pragma unroll
        for (int i = 0; i < 2; i++) {
            float* dst = &Bs[buf][bk[i]][bn * 4];
            dst[0] = to_tf32(rb[i].x); dst[1] = to_tf32(rb[i].y);
            dst[2] = to_tf32(rb[i].z); dst[3] = to_tf32(rb[i].w);
        }
        __syncthreads();

        // Prefetch next tile (overlaps with MMA below)
        if (it + 1 < NITER) {
            const int kt = (it + 1) * 32;
#pragma unroll
            for (int i = 0; i < 4; i++)
                ra[i] = *(const float4*)(Abase + (size_t)ar[i] * Hn + kt + ac * 4);
#pragma unroll
            for (int i = 0; i < 2; i++)
                rb[i] = *(const float4*)(Wbase + (size_t)(kt + bk[i]) * Fn + bn * 4);
        }

#pragma unroll
        for (int ks = 0; ks < 4; ks++) {
            uint32_t af[2][4], bf[4][2];
            const int k0 = ks * 8 + tig;
#pragma unroll
            for (int mt = 0; mt < 2; mt++) {
                int r0 = warpM * 32 + mt * 16 + g;
                af[mt][0] = __float_as_uint(As[buf][r0][k0]);
                af[mt][1] = __float_as_uint(As[buf][r0 + 8][k0]);
                af[mt][2] = __float_as_uint(As[buf][r0][k0 + 4]);
                af[mt][3] = __float_as_uint(As[buf][r0 + 8][k0 + 4]);
            }
#pragma unroll
            for (int nt = 0; nt < 4; nt++) {
                int n0 = warpN * 32 + nt * 8 + g;
                bf[nt][0] = __float_as_uint(Bs[buf][k0][n0]);
                bf[nt][1] = __float_as_uint(Bs[buf][k0 + 4][n0]);
            }
#pragma unroll
            for (int mt = 0; mt < 2; mt++)
#pragma unroll
                for (int nt = 0; nt < 4; nt++) {
                    asm volatile(
                        "mma.sync.aligned.m16n8k8.row.col.f32.tf32.tf32.f32 "
                        "{%0,%1,%2,%3}, {%4,%5,%6,%7}, {%8,%9}, {%0,%1,%2,%3};"
                        : "+f"(c[mt][nt][0]), "+f"(c[mt][nt][1]),
                          "+f"(c[mt][nt][2]), "+f"(c[mt][nt][3])
                        : "r"(af[mt][0]), "r"(af[mt][1]),
                          "r"(af[mt][2]), "r"(af[mt][3]),
                          "r"(bf[nt][0]), "r"(bf[nt][1]));
                }
        }
        // No trailing sync needed: writes to buf^1 at iter it+1 are ordered
        // after this iteration's barrier, and last reads of buf^1 were at
        // iter it-1, before that barrier.
        __syncthreads();
    }

    // Epilogue: thread owns C[row(+8)][col, col+1] per (mt, nt) tile.
#pragma unroll
    for (int nt = 0; nt < 4; nt++) {
        int col = warpN * 32 + nt * 8 + 2 * tig;
        float b0 = 0.0f, b1 = 0.0f;
        if (is_audio) {
            b0 = bias[bc * 64 + col];
            b1 = bias[bc * 64 + col + 1];
        }
#pragma unroll
        for (int mt = 0; mt < 2; mt++) {
            int row = warpM * 32 + mt * 16 + g;
            float2 v0, v1;
            v0.x = c[mt][nt][0] + b0; v0.y = c[mt][nt][1] + b1;
            v1.x = c[mt][nt][2] + b0; v1.y = c[mt][nt][3] + b1;
            *(float2*)(Cbase + (size_t)row * Fn + col) = v0;
            *(float2*)(Cbase + (size_t)(row + 8) * Fn + col) = v1;
        }
    }
}

// ---------------------------------------------------------------------------
// Kernel 2: broadcast add. out[b,t,u,f] = a[b,t,f] + l[b,u,f].
// CTA tile: 8 t x 64 u x 128 f. SMEM-staged a (4KB) and l (32KB).
// 5 CTAs/SM for more outstanding store streams; streaming stores (.cs).
// ---------------------------------------------------------------------------
__global__ __launch_bounds__(256, 5)
void joint_bcast_kernel(float* __restrict__ out)
{
    const int fb = blockIdx.x;    // 0..7  -> f tile of 128
    const int tb = blockIdx.y;    // 0..31 -> t tile of 8
    const int b  = blockIdx.z;    // 0..7

    __shared__ float sa[8][128];
    __shared__ float sl[64][128];

    const int tid = threadIdx.x;

    // Load a tile: 8 rows x 128 f = 256 float4, 1 per thread.
    {
        int r = tid >> 5, c = tid & 31;
        const float4* src = (const float4*)(g_a + ((size_t)(b * Tn + tb * 8 + r) * Fn) + fb * 128);
        ((float4*)sa[r])[c] = src[c];
    }
    // Load l tile: 64 rows x 128 f = 2048 float4, 8 per thread.
#pragma unroll
    for (int i = 0; i < 8; i++) {
        int id = tid + i * 256;
        int r = id >> 5, c = id & 31;
        const float4* src = (const float4*)(g_l + ((size_t)(b * Un + r) * Fn) + fb * 128);
        ((float4*)sl[r])[c] = src[c];
    }
    __syncthreads();

    const int r = tid >> 5;       // warp id
    const int c = tid & 31;       // float4 lane within the 128-f row
    const size_t bt0 = (size_t)b * Tn + (size_t)tb * 8;
    float4* out4 = (float4*)out;
    const size_t base = bt0 * Un * (Fn / 4) + (size_t)fb * 32 + c;

    // 512 (t,u) rows per CTA, 8 rows (one per warp) per iteration.
#pragma unroll 2
    for (int it = 0; it < 64; it++) {
        int rowLocal = it * 8 + r;          // 0..511
        int t = rowLocal >> 6;              // 0..7
        int u = rowLocal & 63;              // 0..63
        float4 va = ((const float4*)sa[t])[c];
        float4 vl = ((const float4*)sl[u])[c];
        float4 v;
        v.x = va.x + vl.x; v.y = va.y + vl.y;
        v.z = va.z + vl.z; v.w = va.w + vl.w;
        __stcs(&out4[base + (size_t)rowLocal * (Fn / 4)], v);
    }
}

// ---------------------------------------------------------------------------
extern "C" void kernel_launch(void* const* d_in, const int* in_sizes, int n_in,
                              void* d_out, int out_size)
{
    const float* audio = (const float*)d_in[0];   // (8,256,512)
    const float* label = (const float*)d_in[1];   // (8,64,512)
    const float* W     = (const float*)d_in[2];   // (1024,1024)
    const float* bias  = (const float*)d_in[3];   // (1024,)
    float* out = (float*)d_out;                   // (8,256,64,1024)

    dim3 ggrid(Fn / 64, (Bn * Tn + Bn * Un) / 128);    // (16, 20)
    joint_gemm_tc<<<ggrid, 256>>>(audio, label, W, bias);

    dim3 bgrid(Fn / 128, Tn / 8, Bn);                  // (8, 32, 8)
    joint_bcast_kernel<<<bgrid, 256>>>(out);
}